// round 10
// baseline (speedup 1.0000x reference)
#include <cuda_runtime.h>
#include <cuda_fp16.h>
#include <cstdint>
#include <math.h>

// Problem constants (fixed by the dataset)
#define S_LEN  8192
#define B_SZ   2
#define DM     1024
#define NH     16
#define DH     64
#define SEG    128
#define NSEG   (S_LEN / SEG)     // 64
#define GRID_G 91                // ceil(sqrt(8192))

#define MROWS  (B_SZ * S_LEN)      // 16384
#define KVROWS (B_SZ * S_LEN / 2)  // 8192 compacted K/V rows

// ---------------------------------------------------------------------------
// Scratch (allocation-free rule: __device__ globals)
// ---------------------------------------------------------------------------
__device__ __half  g_x   [MROWS * DM];          // x fp16
__device__ __half  g_q   [MROWS * DM];          // Q fp16 single
__device__ __half  g_kv  [KVROWS * 2 * DM];     // compact [K|V] fp16
__device__ __half  g_a   [MROWS * DM];          // attn-out fp16
__device__ __half  g_wq  [3 * DM * DM];         // W_qkv^T fp16 [3072,1024]
__device__ __half  g_wo  [DM * DM];             // W_out^T fp16 [1024,1024]
__device__ int     g_rowkv[KVROWS];             // gathered A rows for K/V GEMM

// ---------------------------------------------------------------------------
// PTX helpers (compute_103-safe subset: ldmatrix / mma.sync / cp.async)
// ---------------------------------------------------------------------------
__device__ __forceinline__ uint32_t smem_to_u32(const void* p) {
    uint32_t a;
    asm("{ .reg .u64 t; cvta.to.shared.u64 t, %1; cvt.u32.u64 %0, t; }"
        : "=r"(a) : "l"(p));
    return a;
}
__device__ __forceinline__ void cp_async16(uint32_t saddr, const void* gptr) {
    asm volatile("cp.async.cg.shared.global [%0], [%1], 16;"
                 :: "r"(saddr), "l"(gptr));
}
#define CP_COMMIT() asm volatile("cp.async.commit_group;")
#define CP_WAIT(n)  asm volatile("cp.async.wait_group %0;" :: "n"(n))

__device__ __forceinline__ void ldsm_x4(uint32_t& r0, uint32_t& r1,
                                        uint32_t& r2, uint32_t& r3,
                                        uint32_t addr) {
    asm volatile("ldmatrix.sync.aligned.m8n8.x4.shared.b16 {%0,%1,%2,%3}, [%4];"
                 : "=r"(r0), "=r"(r1), "=r"(r2), "=r"(r3) : "r"(addr));
}
__device__ __forceinline__ void ldsm_x4_t(uint32_t& r0, uint32_t& r1,
                                          uint32_t& r2, uint32_t& r3,
                                          uint32_t addr) {
    asm volatile("ldmatrix.sync.aligned.m8n8.x4.trans.shared.b16 {%0,%1,%2,%3}, [%4];"
                 : "=r"(r0), "=r"(r1), "=r"(r2), "=r"(r3) : "r"(addr));
}
__device__ __forceinline__ void mma16816(float* c,
                                         uint32_t a0, uint32_t a1,
                                         uint32_t a2, uint32_t a3,
                                         uint32_t b0, uint32_t b1) {
    asm volatile(
        "mma.sync.aligned.m16n8k16.row.col.f32.f16.f16.f32 "
        "{%0,%1,%2,%3}, {%4,%5,%6,%7}, {%8,%9}, {%0,%1,%2,%3};"
        : "+f"(c[0]), "+f"(c[1]), "+f"(c[2]), "+f"(c[3])
        : "r"(a0), "r"(a1), "r"(a2), "r"(a3), "r"(b0), "r"(b1));
}

__device__ __forceinline__ uint32_t pack_h2(float a, float b) {
    __half2 t = __halves2half2(__float2half_rn(a), __float2half_rn(b));
    return *(uint32_t*)&t;
}

// ---------------------------------------------------------------------------
// Closed-form boustrophedon map
// ---------------------------------------------------------------------------
__device__ __forceinline__ int hmap(int lp) {
    int r = lp / GRID_G;
    int c = lp % GRID_G;
    int vr = min(GRID_G, S_LEN - r * GRID_G);
    return ((r & 1) == 0) ? (r * GRID_G + c) : (r * GRID_G + vr - 1 - c);
}

// ---------------------------------------------------------------------------
// Merged prep: cvt (16384 blocks) | W_qkv^T (3072) | W_out^T (1024) | rowkv (32)
// All blocks 256 threads.
// ---------------------------------------------------------------------------
#define PREP_CVT_BLKS   16384
#define PREP_TQ_BLKS    3072
#define PREP_TO_BLKS    1024
#define PREP_RK_BLKS    32
#define PREP_BLKS (PREP_CVT_BLKS + PREP_TQ_BLKS + PREP_TO_BLKS + PREP_RK_BLKS)

__global__ __launch_bounds__(256) void prep_kernel(
    const float* __restrict__ x,
    const float* __restrict__ wqkv,
    const float* __restrict__ wout)
{
    __shared__ float t[32][33];
    const int bx = blockIdx.x;
    const int tid = threadIdx.x;

    if (bx < PREP_CVT_BLKS) {
        // fp32 -> fp16 convert of x
        int i = bx * 256 + tid;      // < MROWS*DM/4 exactly
        float4 v = ((const float4*)x)[i];
        ((uint32_t*)g_x)[2 * i]     = pack_h2(v.x, v.y);
        ((uint32_t*)g_x)[2 * i + 1] = pack_h2(v.z, v.w);
        return;
    }
    if (bx < PREP_CVT_BLKS + PREP_TQ_BLKS + PREP_TO_BLKS) {
        // tiled transpose + cvt of W_qkv (N=3072) or W_out (N=1024)
        const float* W; __half* T; int N, tb;
        if (bx < PREP_CVT_BLKS + PREP_TQ_BLKS) {
            W = wqkv; T = g_wq; N = 3 * DM; tb = bx - PREP_CVT_BLKS;
        } else {
            W = wout; T = g_wo; N = DM; tb = bx - PREP_CVT_BLKS - PREP_TQ_BLKS;
        }
        int nblk = N / 32;
        int n0 = (tb % nblk) * 32, k0 = (tb / nblk) * 32;
        int tx = tid & 31, ty = tid >> 5;   // (32, 8)
        #pragma unroll
        for (int i = 0; i < 4; i++)
            t[ty + 8 * i][tx] = W[(size_t)(k0 + ty + 8 * i) * N + n0 + tx];
        __syncthreads();
        #pragma unroll
        for (int i = 0; i < 4; i++) {
            size_t o = (size_t)(n0 + ty + 8 * i) * DM + k0 + tx;
            T[o] = __float2half_rn(t[tx][ty + 8 * i]);
        }
        return;
    }
    // rowkv
    int i = (bx - (PREP_BLKS - PREP_RK_BLKS)) * 256 + tid;  // < KVROWS exactly
    int b = i >> 12;
    int r = i & 4095;
    int n = r >> 6, j = r & 63;
    g_rowkv[i] = b * S_LEN + hmap(n * SEG + 2 * j);
}

// ---------------------------------------------------------------------------
// GEMM core (BN=256): tile (m0,n0) of C[?,N] = A[rows][1024] @ B[N,1024]^T
// BM=128, BK=32, 256 threads, 4-stage cp.async. fp16-single output.
// ---------------------------------------------------------------------------
#define GBM 128
#define GBK 32
#define KD  1024
#define ITERS (KD / GBK)               // 32
#define RSB 80                         // 32 fp16 + 8 pad = 80 bytes/row
#define NSTAGE  4

#define OFF_B256   (GBM * RSB)              // 10240
#define STAGE256   ((GBM + 256) * RSB)      // 30720
#define SMEM256    (NSTAGE * STAGE256)      // 122880

__device__ __forceinline__ void gemm_core256(
    int m0, int n0, int N,
    const __half* __restrict__ A, const __half* __restrict__ B,
    const int* __restrict__ rowlist,
    __half* __restrict__ Ch,
    char* smem, int* srl)
{
    const uint32_t sb = smem_to_u32(smem);
    const int tid  = threadIdx.x;
    const int wid  = tid >> 5;
    const int lane = tid & 31;

    if (tid < GBM) srl[tid] = rowlist ? rowlist[m0 + tid] : (m0 + tid);
    __syncthreads();

    const int warp_m = (wid & 1) * 64;
    const int warp_n = (wid >> 1) * 64;

    float acc[4][8][4];
    #pragma unroll
    for (int i = 0; i < 4; i++)
        #pragma unroll
        for (int j = 0; j < 8; j++)
            #pragma unroll
            for (int q = 0; q < 4; q++) acc[i][j][q] = 0.0f;

    auto load_stage = [&](int it, int stage) {
        const uint32_t stg = sb + stage * STAGE256;
        const int k0 = it * GBK;
        #pragma unroll
        for (int i = 0; i < 6; i++) {
            int c = i * 256 + tid;
            const __half* g;
            uint32_t soff;
            if (c < 512) {
                int row = c >> 2, kc = c & 3;
                g = A + (size_t)srl[row] * KD + k0 + kc * 8;
                soff = row * RSB + kc * 16;
            } else {
                int c2 = c - 512;
                int row = c2 >> 2, kc = c2 & 3;
                g = B + (size_t)(n0 + row) * KD + k0 + kc * 8;
                soff = OFF_B256 + row * RSB + kc * 16;
            }
            cp_async16(stg + soff, g);
        }
    };

    load_stage(0, 0); CP_COMMIT();
    load_stage(1, 1); CP_COMMIT();
    load_stage(2, 2); CP_COMMIT();

    const int a_row  = lane & 15;
    const int a_byte = (lane >> 4) << 4;
    const int b_row  = ((lane >> 4) << 3) + (lane & 7);
    const int b_byte = ((lane >> 3) & 1) << 4;

    #pragma unroll 1
    for (int it = 0; it < ITERS; ++it) {
        if (it + 1 >= ITERS)      { CP_WAIT(0); }
        else if (it + 2 >= ITERS) { CP_WAIT(1); }
        else                      { CP_WAIT(2); }
        __syncthreads();

        if (it + 3 < ITERS) {
            load_stage(it + 3, (it + 3) & (NSTAGE - 1));
            CP_COMMIT();
        }

        const uint32_t stg = sb + (it & (NSTAGE - 1)) * STAGE256;
        const uint32_t aARow = stg + (warp_m + a_row) * RSB + a_byte;
        const uint32_t aBRow = stg + OFF_B256 + (warp_n + b_row) * RSB + b_byte;

        #pragma unroll
        for (int kc = 0; kc < 2; kc++) {
            const uint32_t kb = kc * 32;
            uint32_t aa[4][4], bb[8][2];
            #pragma unroll
            for (int i = 0; i < 4; i++)
                ldsm_x4(aa[i][0], aa[i][1], aa[i][2], aa[i][3],
                        aARow + i * 16 * RSB + kb);
            #pragma unroll
            for (int jj = 0; jj < 4; jj++)
                ldsm_x4(bb[2*jj][0], bb[2*jj][1], bb[2*jj+1][0], bb[2*jj+1][1],
                        aBRow + jj * 16 * RSB + kb);
            #pragma unroll
            for (int i = 0; i < 4; i++)
                #pragma unroll
                for (int j = 0; j < 8; j++)
                    mma16816(acc[i][j], aa[i][0], aa[i][1], aa[i][2], aa[i][3],
                             bb[j][0], bb[j][1]);
        }
    }

    const int er = lane >> 2;
    const int ec = (lane & 3) * 2;
    #pragma unroll
    for (int i = 0; i < 4; i++)
        #pragma unroll
        for (int j = 0; j < 8; j++) {
            int row = m0 + warp_m + i * 16 + er;
            int col = n0 + warp_n + j * 8 + ec;
            *(uint32_t*)(Ch + (size_t)row * N + col) =
                pack_h2(acc[i][j][0], acc[i][j][1]);
            *(uint32_t*)(Ch + (size_t)(row + 8) * N + col) =
                pack_h2(acc[i][j][2], acc[i][j][3]);
        }
}

// Merged Q + K/V projection: 1024 CTAs.
__global__ __launch_bounds__(256, 1) void gemm_qkv() {
    extern __shared__ char smem[];
    __shared__ int srl[GBM];
    int bx = blockIdx.x;
    if (bx < 512) {
        gemm_core256((bx >> 2) * GBM, (bx & 3) * 256, DM,
                     g_x, g_wq, nullptr, g_q, smem, srl);
    } else {
        int t = bx - 512;
        gemm_core256((t >> 3) * GBM, (t & 7) * 256, 2 * DM,
                     g_x, g_wq + (size_t)DM * DM, g_rowkv, g_kv, smem, srl);
    }
}

// ---------------------------------------------------------------------------
// Output projection (BN=128 -> 1024 CTAs, ~1% wave tail), fp32 out.
// Warp tile 64x32: warp_m = (wid&1)*64, warp_n = (wid>>1)*32.
// ---------------------------------------------------------------------------
#define OFF_B128   (GBM * RSB)              // 10240
#define STAGE128   ((GBM + 128) * RSB)      // 20480
#define SMEM128    (NSTAGE * STAGE128)      // 81920

__global__ __launch_bounds__(256, 1) void gemm_out(float* __restrict__ C) {
    extern __shared__ char smem[];
    const uint32_t sb = smem_to_u32(smem);
    const int tid  = threadIdx.x;
    const int wid  = tid >> 5;
    const int lane = tid & 31;

    const int m0 = (blockIdx.x >> 3) * GBM;
    const int n0 = (blockIdx.x & 7) * 128;

    const int warp_m = (wid & 1) * 64;
    const int warp_n = (wid >> 1) * 32;

    float acc[4][4][4];
    #pragma unroll
    for (int i = 0; i < 4; i++)
        #pragma unroll
        for (int j = 0; j < 4; j++)
            #pragma unroll
            for (int q = 0; q < 4; q++) acc[i][j][q] = 0.0f;

    auto load_stage = [&](int it, int stage) {
        const uint32_t stg = sb + stage * STAGE128;
        const int k0 = it * GBK;
        #pragma unroll
        for (int i = 0; i < 4; i++) {
            int c = i * 256 + tid;
            const __half* g;
            uint32_t soff;
            if (c < 512) {
                int row = c >> 2, kc = c & 3;
                g = g_a + (size_t)(m0 + row) * KD + k0 + kc * 8;
                soff = row * RSB + kc * 16;
            } else {
                int c2 = c - 512;
                int row = c2 >> 2, kc = c2 & 3;
                g = g_wo + (size_t)(n0 + row) * KD + k0 + kc * 8;
                soff = OFF_B128 + row * RSB + kc * 16;
            }
            cp_async16(stg + soff, g);
        }
    };

    load_stage(0, 0); CP_COMMIT();
    load_stage(1, 1); CP_COMMIT();
    load_stage(2, 2); CP_COMMIT();

    const int a_row  = lane & 15;
    const int a_byte = (lane >> 4) << 4;
    const int b_row  = ((lane >> 4) << 3) + (lane & 7);
    const int b_byte = ((lane >> 3) & 1) << 4;

    #pragma unroll 1
    for (int it = 0; it < ITERS; ++it) {
        if (it + 1 >= ITERS)      { CP_WAIT(0); }
        else if (it + 2 >= ITERS) { CP_WAIT(1); }
        else                      { CP_WAIT(2); }
        __syncthreads();

        if (it + 3 < ITERS) {
            load_stage(it + 3, (it + 3) & (NSTAGE - 1));
            CP_COMMIT();
        }

        const uint32_t stg = sb + (it & (NSTAGE - 1)) * STAGE128;
        const uint32_t aARow = stg + (warp_m + a_row) * RSB + a_byte;
        const uint32_t aBRow = stg + OFF_B128 + (warp_n + b_row) * RSB + b_byte;

        #pragma unroll
        for (int kc = 0; kc < 2; kc++) {
            const uint32_t kb = kc * 32;
            uint32_t aa[4][4], bb[4][2];
            #pragma unroll
            for (int i = 0; i < 4; i++)
                ldsm_x4(aa[i][0], aa[i][1], aa[i][2], aa[i][3],
                        aARow + i * 16 * RSB + kb);
            #pragma unroll
            for (int jj = 0; jj < 2; jj++)
                ldsm_x4(bb[2*jj][0], bb[2*jj][1], bb[2*jj+1][0], bb[2*jj+1][1],
                        aBRow + jj * 16 * RSB + kb);
            #pragma unroll
            for (int i = 0; i < 4; i++)
                #pragma unroll
                for (int j = 0; j < 4; j++)
                    mma16816(acc[i][j], aa[i][0], aa[i][1], aa[i][2], aa[i][3],
                             bb[j][0], bb[j][1]);
        }
    }

    const int er = lane >> 2;
    const int ec = (lane & 3) * 2;
    #pragma unroll
    for (int i = 0; i < 4; i++)
        #pragma unroll
        for (int j = 0; j < 4; j++) {
            int row = m0 + warp_m + i * 16 + er;
            int col = n0 + warp_n + j * 8 + ec;
            float* p0 = C + (size_t)row * DM + col;
            float* p1 = C + (size_t)(row + 8) * DM + col;
            p0[0] = acc[i][j][0]; p0[1] = acc[i][j][1];
            p1[0] = acc[i][j][2]; p1[1] = acc[i][j][3];
        }
}

// ---------------------------------------------------------------------------
// Tensor-core segment attention (fp16 HMMA, softmax in fragments).
// Q, K, V, P all single fp16.  One block per (b, h, seg): 128 threads.
// smem: swizzled fp16 tiles Q[128x64], K[64x64], V[64x64] = 32KB.
// ---------------------------------------------------------------------------
#define ASM_Q  0
#define ASM_K  16384
#define ASM_V  24576
#define ATTN_SMEM 32768
#define SWIZ(base, row, ch) ((base) + (row) * 128 + ((((ch) ^ ((row) & 7))) << 4))

__global__ __launch_bounds__(128) void attn_kernel() {
    extern __shared__ char asmem[];
    const uint32_t sb = smem_to_u32(asmem);

    const int bid = blockIdx.x;
    const int n = bid % NSEG;
    const int h = (bid / NSEG) % NH;
    const int b = bid / (NSEG * NH);
    const int tid = threadIdx.x;
    const int lane = tid & 31;
    const int wid = tid >> 5;
    const int warp_m = wid * 32;

    // ---- load Q: 1024 16B chunks ----
    #pragma unroll
    for (int i = 0; i < 8; i++) {
        int c = i * 128 + tid;
        int row = c >> 3, ch = c & 7;
        int sq = hmap(n * SEG + row);
        const __half* g = g_q + ((size_t)(b * S_LEN + sq)) * DM + h * DH + ch * 8;
        cp_async16(SWIZ(sb + ASM_Q, row, ch), g);
    }
    // ---- load K and V: 1024 16B chunks ----
    #pragma unroll
    for (int i = 0; i < 8; i++) {
        int c = i * 128 + tid;
        int kv  = c >> 9;
        int rc  = c & 511;
        int row = rc >> 3, ch = rc & 7;
        size_t go = ((size_t)b * 4096 + n * 64 + row) * (2 * DM)
                  + (size_t)kv * DM + h * DH + ch * 8;
        cp_async16(SWIZ(sb + (kv ? ASM_V : ASM_K), row, ch), g_kv + go);
    }
    CP_COMMIT();
    CP_WAIT(0);
    __syncthreads();

    // ---- scores: S = Q @ K^T ----
    float acc_s[2][8][4];
    #pragma unroll
    for (int i = 0; i < 2; i++)
        #pragma unroll
        for (int j = 0; j < 8; j++)
            #pragma unroll
            for (int q = 0; q < 4; q++) acc_s[i][j][q] = 0.0f;

    const int a_r  = lane & 15;
    const int a_c  = lane >> 4;
    const int b_r  = ((lane >> 4) << 3) + (lane & 7);
    const int b_c  = (lane >> 3) & 1;

    #pragma unroll
    for (int t = 0; t < 4; t++) {
        uint32_t qq[2][4], kk[8][2];
        #pragma unroll
        for (int i = 0; i < 2; i++) {
            int row = warp_m + i * 16 + a_r;
            int ch = 2 * t + a_c;
            ldsm_x4(qq[i][0], qq[i][1], qq[i][2], qq[i][3],
                    SWIZ(sb + ASM_Q, row, ch));
        }
        #pragma unroll
        for (int jj = 0; jj < 4; jj++) {
            int row = jj * 16 + b_r;
            int ch = 2 * t + b_c;
            ldsm_x4(kk[2*jj][0], kk[2*jj][1], kk[2*jj+1][0], kk[2*jj+1][1],
                    SWIZ(sb + ASM_K, row, ch));
        }
        #pragma unroll
        for (int i = 0; i < 2; i++)
            #pragma unroll
            for (int j = 0; j < 8; j++)
                mma16816(acc_s[i][j], qq[i][0], qq[i][1], qq[i][2], qq[i][3],
                         kk[j][0], kk[j][1]);
    }

    // ---- softmax over 64 cols, per fragment row (quad shfl reduce) ----
    #pragma unroll
    for (int i = 0; i < 2; i++) {
        #pragma unroll
        for (int half = 0; half < 2; half++) {
            float mx = -1e30f;
            #pragma unroll
            for (int j = 0; j < 8; j++) {
                mx = fmaxf(mx, acc_s[i][j][half*2]);
                mx = fmaxf(mx, acc_s[i][j][half*2+1]);
            }
            mx = fmaxf(mx, __shfl_xor_sync(0xffffffffu, mx, 1));
            mx = fmaxf(mx, __shfl_xor_sync(0xffffffffu, mx, 2));
            float sum = 0.0f;
            #pragma unroll
            for (int j = 0; j < 8; j++) {
                float p0 = expf((acc_s[i][j][half*2]   - mx) * 0.125f);
                float p1 = expf((acc_s[i][j][half*2+1] - mx) * 0.125f);
                acc_s[i][j][half*2]   = p0;
                acc_s[i][j][half*2+1] = p1;
                sum += p0 + p1;
            }
            sum += __shfl_xor_sync(0xffffffffu, sum, 1);
            sum += __shfl_xor_sync(0xffffffffu, sum, 2);
            float inv = 1.0f / sum;
            #pragma unroll
            for (int j = 0; j < 8; j++) {
                acc_s[i][j][half*2]   *= inv;
                acc_s[i][j][half*2+1] *= inv;
            }
        }
    }

    // ---- O = P @ V  (P single fp16 in frags, V^T via ldmatrix.trans) ----
    float acc_o[2][8][4];
    #pragma unroll
    for (int i = 0; i < 2; i++)
        #pragma unroll
        for (int j = 0; j < 8; j++)
            #pragma unroll
            for (int q = 0; q < 4; q++) acc_o[i][j][q] = 0.0f;

    #pragma unroll
    for (int t = 0; t < 4; t++) {
        uint32_t pp[2][4];
        #pragma unroll
        for (int i = 0; i < 2; i++) {
            pp[i][0] = pack_h2(acc_s[i][2*t][0],   acc_s[i][2*t][1]);
            pp[i][1] = pack_h2(acc_s[i][2*t][2],   acc_s[i][2*t][3]);
            pp[i][2] = pack_h2(acc_s[i][2*t+1][0], acc_s[i][2*t+1][1]);
            pp[i][3] = pack_h2(acc_s[i][2*t+1][2], acc_s[i][2*t+1][3]);
        }
        uint32_t vv[8][2];
        #pragma unroll
        for (int jj = 0; jj < 4; jj++) {
            int row = t * 16 + (lane & 15);
            int ch = jj * 2 + (lane >> 4);
            ldsm_x4_t(vv[2*jj][0], vv[2*jj][1], vv[2*jj+1][0], vv[2*jj+1][1],
                      SWIZ(sb + ASM_V, row, ch));
        }
        #pragma unroll
        for (int i = 0; i < 2; i++)
            #pragma unroll
            for (int nd = 0; nd < 8; nd++)
                mma16816(acc_o[i][nd], pp[i][0], pp[i][1], pp[i][2], pp[i][3],
                         vv[nd][0], vv[nd][1]);
    }

    // ---- epilogue: scatter rows back by map, write single fp16 ----
    const int er = lane >> 2;
    const int ec = (lane & 3) * 2;
    #pragma unroll
    for (int i = 0; i < 2; i++) {
        #pragma unroll
        for (int half = 0; half < 2; half++) {
            int rowl = warp_m + i * 16 + er + half * 8;
            int sq = hmap(n * SEG + rowl);
            size_t gr = ((size_t)(b * S_LEN + sq)) * DM + h * DH;
            #pragma unroll
            for (int nd = 0; nd < 8; nd++) {
                *(uint32_t*)(g_a + gr + nd * 8 + ec) =
                    pack_h2(acc_o[i][nd][half*2], acc_o[i][nd][half*2+1]);
            }
        }
    }
}

// ---------------------------------------------------------------------------
// Launch
// ---------------------------------------------------------------------------
extern "C" void kernel_launch(void* const* d_in, const int* in_sizes, int n_in,
                              void* d_out, int out_size)
{
    const float* x    = (const float*)d_in[0];   // [2,8192,1024]
    const float* wqkv = (const float*)d_in[1];   // [1024,3072]
    const float* wout = (const float*)d_in[2];   // [1024,1024]
    float*       out  = (float*)d_out;           // [2,8192,1024]

    static bool attr_set = false;
    if (!attr_set) {
        cudaFuncSetAttribute(gemm_qkv,
            cudaFuncAttributeMaxDynamicSharedMemorySize, SMEM256);
        cudaFuncSetAttribute(gemm_out,
            cudaFuncAttributeMaxDynamicSharedMemorySize, SMEM128);
        cudaFuncSetAttribute(attn_kernel,
            cudaFuncAttributeMaxDynamicSharedMemorySize, ATTN_SMEM);
        attr_set = true;
    }

    // 1. merged prep (one launch)
    prep_kernel<<<PREP_BLKS, 256>>>(x, wqkv, wout);

    // 2. merged Q + K/V projections (1024 CTAs)
    gemm_qkv<<<1024, 256, SMEM256>>>();

    // 3. tensor-core segment attention -> fp16 single
    attn_kernel<<<B_SZ * NH * NSEG, 128, ATTN_SMEM>>>();

    // 4. output projection -> fp32 final (1024 CTAs, BN=128)
    gemm_out<<<1024, 256, SMEM128>>>(out);
}

// round 11
// speedup vs baseline: 1.2688x; 1.2688x over previous
#include <cuda_runtime.h>
#include <cuda_fp16.h>
#include <cstdint>
#include <math.h>

// Problem constants (fixed by the dataset)
#define S_LEN  8192
#define B_SZ   2
#define DM     1024
#define NH     16
#define DH     64
#define SEG    128
#define NSEG   (S_LEN / SEG)     // 64
#define GRID_G 91                // ceil(sqrt(8192))

#define MROWS  (B_SZ * S_LEN)      // 16384
#define KVROWS (B_SZ * S_LEN / 2)  // 8192 compacted K/V rows

// ---------------------------------------------------------------------------
// Scratch (allocation-free rule: __device__ globals)
// ---------------------------------------------------------------------------
__device__ __half  g_x   [MROWS * DM];          // x fp16
__device__ __half  g_q   [MROWS * DM];          // Q fp16 single
__device__ __half  g_kv  [KVROWS * 2 * DM];     // compact [K|V] fp16
__device__ __half  g_a   [MROWS * DM];          // attn-out fp16
__device__ __half  g_wq  [3 * DM * DM];         // W_qkv^T fp16 [3072,1024]
__device__ __half  g_wo  [DM * DM];             // W_out^T fp16 [1024,1024]
__device__ int     g_rowkv[KVROWS];             // gathered A rows for K/V GEMM

// ---------------------------------------------------------------------------
// PTX helpers (compute_103-safe subset: ldmatrix / mma.sync / cp.async)
// ---------------------------------------------------------------------------
__device__ __forceinline__ uint32_t smem_to_u32(const void* p) {
    uint32_t a;
    asm("{ .reg .u64 t; cvta.to.shared.u64 t, %1; cvt.u32.u64 %0, t; }"
        : "=r"(a) : "l"(p));
    return a;
}
__device__ __forceinline__ void cp_async16(uint32_t saddr, const void* gptr) {
    asm volatile("cp.async.cg.shared.global [%0], [%1], 16;"
                 :: "r"(saddr), "l"(gptr));
}
#define CP_COMMIT() asm volatile("cp.async.commit_group;")
#define CP_WAIT(n)  asm volatile("cp.async.wait_group %0;" :: "n"(n))

__device__ __forceinline__ void ldsm_x4(uint32_t& r0, uint32_t& r1,
                                        uint32_t& r2, uint32_t& r3,
                                        uint32_t addr) {
    asm volatile("ldmatrix.sync.aligned.m8n8.x4.shared.b16 {%0,%1,%2,%3}, [%4];"
                 : "=r"(r0), "=r"(r1), "=r"(r2), "=r"(r3) : "r"(addr));
}
__device__ __forceinline__ void ldsm_x4_t(uint32_t& r0, uint32_t& r1,
                                          uint32_t& r2, uint32_t& r3,
                                          uint32_t addr) {
    asm volatile("ldmatrix.sync.aligned.m8n8.x4.trans.shared.b16 {%0,%1,%2,%3}, [%4];"
                 : "=r"(r0), "=r"(r1), "=r"(r2), "=r"(r3) : "r"(addr));
}
__device__ __forceinline__ void mma16816(float* c,
                                         uint32_t a0, uint32_t a1,
                                         uint32_t a2, uint32_t a3,
                                         uint32_t b0, uint32_t b1) {
    asm volatile(
        "mma.sync.aligned.m16n8k16.row.col.f32.f16.f16.f32 "
        "{%0,%1,%2,%3}, {%4,%5,%6,%7}, {%8,%9}, {%0,%1,%2,%3};"
        : "+f"(c[0]), "+f"(c[1]), "+f"(c[2]), "+f"(c[3])
        : "r"(a0), "r"(a1), "r"(a2), "r"(a3), "r"(b0), "r"(b1));
}

__device__ __forceinline__ uint32_t pack_h2(float a, float b) {
    __half2 t = __halves2half2(__float2half_rn(a), __float2half_rn(b));
    return *(uint32_t*)&t;
}

// ---------------------------------------------------------------------------
// Closed-form boustrophedon map
// ---------------------------------------------------------------------------
__device__ __forceinline__ int hmap(int lp) {
    int r = lp / GRID_G;
    int c = lp % GRID_G;
    int vr = min(GRID_G, S_LEN - r * GRID_G);
    return ((r & 1) == 0) ? (r * GRID_G + c) : (r * GRID_G + vr - 1 - c);
}

// ---------------------------------------------------------------------------
// Merged prep: cvt (16384 blocks) | W_qkv^T (3072) | W_out^T (1024) | rowkv (32)
// ---------------------------------------------------------------------------
#define PREP_CVT_BLKS   16384
#define PREP_TQ_BLKS    3072
#define PREP_TO_BLKS    1024
#define PREP_RK_BLKS    32
#define PREP_BLKS (PREP_CVT_BLKS + PREP_TQ_BLKS + PREP_TO_BLKS + PREP_RK_BLKS)

__global__ __launch_bounds__(256) void prep_kernel(
    const float* __restrict__ x,
    const float* __restrict__ wqkv,
    const float* __restrict__ wout)
{
    __shared__ float t[32][33];
    const int bx = blockIdx.x;
    const int tid = threadIdx.x;

    if (bx < PREP_CVT_BLKS) {
        int i = bx * 256 + tid;
        float4 v = ((const float4*)x)[i];
        ((uint32_t*)g_x)[2 * i]     = pack_h2(v.x, v.y);
        ((uint32_t*)g_x)[2 * i + 1] = pack_h2(v.z, v.w);
        return;
    }
    if (bx < PREP_CVT_BLKS + PREP_TQ_BLKS + PREP_TO_BLKS) {
        const float* W; __half* T; int N, tb;
        if (bx < PREP_CVT_BLKS + PREP_TQ_BLKS) {
            W = wqkv; T = g_wq; N = 3 * DM; tb = bx - PREP_CVT_BLKS;
        } else {
            W = wout; T = g_wo; N = DM; tb = bx - PREP_CVT_BLKS - PREP_TQ_BLKS;
        }
        int nblk = N / 32;
        int n0 = (tb % nblk) * 32, k0 = (tb / nblk) * 32;
        int tx = tid & 31, ty = tid >> 5;
        #pragma unroll
        for (int i = 0; i < 4; i++)
            t[ty + 8 * i][tx] = W[(size_t)(k0 + ty + 8 * i) * N + n0 + tx];
        __syncthreads();
        #pragma unroll
        for (int i = 0; i < 4; i++) {
            size_t o = (size_t)(n0 + ty + 8 * i) * DM + k0 + tx;
            T[o] = __float2half_rn(t[tx][ty + 8 * i]);
        }
        return;
    }
    int i = (bx - (PREP_BLKS - PREP_RK_BLKS)) * 256 + tid;
    int b = i >> 12;
    int r = i & 4095;
    int n = r >> 6, j = r & 63;
    g_rowkv[i] = b * S_LEN + hmap(n * SEG + 2 * j);
}

// ---------------------------------------------------------------------------
// Unified GEMM core: BM=128, BN=128, BK=32, 256 threads, 4-stage cp.async,
// 2 CTAs/SM (launch_bounds(256,2) caps regs at 128/thread).
// Warp tile 64x32: warp_m=(wid&1)*64, warp_n=(wid>>1)*32, acc 64 regs.
// Output: fp16 single (FP16OUT) or fp32.
// ---------------------------------------------------------------------------
#define GBM 128
#define GBN 128
#define GBK 32
#define KD  1024
#define ITERS (KD / GBK)               // 32
#define RSB 80                         // 32 fp16 + 8 pad
#define OFF_B   (GBM * RSB)            // 10240
#define STAGE_BYTES ((GBM + GBN) * RSB)  // 20480
#define NSTAGE  4
#define GEMM_SMEM (NSTAGE * STAGE_BYTES) // 81920

template<bool FP16OUT>
__device__ __forceinline__ void gemm_core128(
    int m0, int n0, int N,
    const __half* __restrict__ A, const __half* __restrict__ B,
    const int* __restrict__ rowlist,
    float* __restrict__ C, __half* __restrict__ Ch,
    char* smem, int* srl)
{
    const uint32_t sb = smem_to_u32(smem);
    const int tid  = threadIdx.x;
    const int wid  = tid >> 5;
    const int lane = tid & 31;

    if (tid < GBM) srl[tid] = rowlist ? rowlist[m0 + tid] : (m0 + tid);
    __syncthreads();

    const int warp_m = (wid & 1) * 64;
    const int warp_n = (wid >> 1) * 32;

    float acc[4][4][4];
    #pragma unroll
    for (int i = 0; i < 4; i++)
        #pragma unroll
        for (int j = 0; j < 4; j++)
            #pragma unroll
            for (int q = 0; q < 4; q++) acc[i][j][q] = 0.0f;

    // 1024 16B chunks per stage, 4 per thread
    auto load_stage = [&](int it, int stage) {
        const uint32_t stg = sb + stage * STAGE_BYTES;
        const int k0 = it * GBK;
        #pragma unroll
        for (int i = 0; i < 4; i++) {
            int c = i * 256 + tid;
            const __half* g;
            uint32_t soff;
            if (c < 512) {             // A: 128 rows x 4 chunks
                int row = c >> 2, kc = c & 3;
                g = A + (size_t)srl[row] * KD + k0 + kc * 8;
                soff = row * RSB + kc * 16;
            } else {                   // B: 128 rows x 4 chunks
                int c2 = c - 512;
                int row = c2 >> 2, kc = c2 & 3;
                g = B + (size_t)(n0 + row) * KD + k0 + kc * 8;
                soff = OFF_B + row * RSB + kc * 16;
            }
            cp_async16(stg + soff, g);
        }
    };

    load_stage(0, 0); CP_COMMIT();
    load_stage(1, 1); CP_COMMIT();
    load_stage(2, 2); CP_COMMIT();

    const int a_row  = lane & 15;
    const int a_byte = (lane >> 4) << 4;
    const int b_row  = ((lane >> 4) << 3) + (lane & 7);
    const int b_byte = ((lane >> 3) & 1) << 4;

    #pragma unroll 1
    for (int it = 0; it < ITERS; ++it) {
        if (it + 1 >= ITERS)      { CP_WAIT(0); }
        else if (it + 2 >= ITERS) { CP_WAIT(1); }
        else                      { CP_WAIT(2); }
        __syncthreads();

        if (it + 3 < ITERS) {
            load_stage(it + 3, (it + 3) & (NSTAGE - 1));
            CP_COMMIT();
        }

        const uint32_t stg = sb + (it & (NSTAGE - 1)) * STAGE_BYTES;
        const uint32_t aARow = stg + (warp_m + a_row) * RSB + a_byte;
        const uint32_t aBRow = stg + OFF_B + (warp_n + b_row) * RSB + b_byte;

        #pragma unroll
        for (int kc = 0; kc < 2; kc++) {
            const uint32_t kb = kc * 32;
            uint32_t aa[4][4], bb[4][2];
            #pragma unroll
            for (int i = 0; i < 4; i++)
                ldsm_x4(aa[i][0], aa[i][1], aa[i][2], aa[i][3],
                        aARow + i * 16 * RSB + kb);
            #pragma unroll
            for (int jj = 0; jj < 2; jj++)
                ldsm_x4(bb[2*jj][0], bb[2*jj][1], bb[2*jj+1][0], bb[2*jj+1][1],
                        aBRow + jj * 16 * RSB + kb);
            #pragma unroll
            for (int i = 0; i < 4; i++)
                #pragma unroll
                for (int j = 0; j < 4; j++)
                    mma16816(acc[i][j], aa[i][0], aa[i][1], aa[i][2], aa[i][3],
                             bb[j][0], bb[j][1]);
        }
    }

    const int er = lane >> 2;
    const int ec = (lane & 3) * 2;
    if (FP16OUT) {
        #pragma unroll
        for (int i = 0; i < 4; i++)
            #pragma unroll
            for (int j = 0; j < 4; j++) {
                int row = m0 + warp_m + i * 16 + er;
                int col = n0 + warp_n + j * 8 + ec;
                *(uint32_t*)(Ch + (size_t)row * N + col) =
                    pack_h2(acc[i][j][0], acc[i][j][1]);
                *(uint32_t*)(Ch + (size_t)(row + 8) * N + col) =
                    pack_h2(acc[i][j][2], acc[i][j][3]);
            }
    } else {
        #pragma unroll
        for (int i = 0; i < 4; i++)
            #pragma unroll
            for (int j = 0; j < 4; j++) {
                int row = m0 + warp_m + i * 16 + er;
                int col = n0 + warp_n + j * 8 + ec;
                float* p0 = C + (size_t)row * N + col;
                float* p1 = C + (size_t)(row + 8) * N + col;
                p0[0] = acc[i][j][0]; p0[1] = acc[i][j][1];
                p1[0] = acc[i][j][2]; p1[1] = acc[i][j][3];
            }
    }
}

// Merged Q + K/V projection: 2048 CTAs (1024 Q tiles + 1024 KV tiles).
__global__ __launch_bounds__(256, 2) void gemm_qkv() {
    extern __shared__ char smem[];
    __shared__ int srl[GBM];
    int bx = blockIdx.x;
    if (bx < 1024) {
        gemm_core128<true>((bx >> 3) * GBM, (bx & 7) * GBN, DM,
                           g_x, g_wq, nullptr, nullptr, g_q, smem, srl);
    } else {
        int t = bx - 1024;
        gemm_core128<true>((t >> 4) * GBM, (t & 15) * GBN, 2 * DM,
                           g_x, g_wq + (size_t)DM * DM, g_rowkv,
                           nullptr, g_kv, smem, srl);
    }
}

// Output projection: 1024 CTAs, fp32 out.
__global__ __launch_bounds__(256, 2) void gemm_out(float* __restrict__ C) {
    extern __shared__ char smem[];
    __shared__ int srl[GBM];
    int bx = blockIdx.x;
    gemm_core128<false>((bx >> 3) * GBM, (bx & 7) * GBN, DM,
                        g_a, g_wo, nullptr, C, nullptr, smem, srl);
}

// ---------------------------------------------------------------------------
// Tensor-core segment attention (fp16 HMMA, softmax in fragments).
// Q, K, V, P all single fp16.  One block per (b, h, seg): 128 threads.
// smem: swizzled fp16 tiles Q[128x64], K[64x64], V[64x64] = 32KB.
// ---------------------------------------------------------------------------
#define ASM_Q  0
#define ASM_K  16384
#define ASM_V  24576
#define ATTN_SMEM 32768
#define SWIZ(base, row, ch) ((base) + (row) * 128 + ((((ch) ^ ((row) & 7))) << 4))

__global__ __launch_bounds__(128) void attn_kernel() {
    extern __shared__ char asmem[];
    const uint32_t sb = smem_to_u32(asmem);

    const int bid = blockIdx.x;
    const int n = bid % NSEG;
    const int h = (bid / NSEG) % NH;
    const int b = bid / (NSEG * NH);
    const int tid = threadIdx.x;
    const int lane = tid & 31;
    const int wid = tid >> 5;
    const int warp_m = wid * 32;

    #pragma unroll
    for (int i = 0; i < 8; i++) {
        int c = i * 128 + tid;
        int row = c >> 3, ch = c & 7;
        int sq = hmap(n * SEG + row);
        const __half* g = g_q + ((size_t)(b * S_LEN + sq)) * DM + h * DH + ch * 8;
        cp_async16(SWIZ(sb + ASM_Q, row, ch), g);
    }
    #pragma unroll
    for (int i = 0; i < 8; i++) {
        int c = i * 128 + tid;
        int kv  = c >> 9;
        int rc  = c & 511;
        int row = rc >> 3, ch = rc & 7;
        size_t go = ((size_t)b * 4096 + n * 64 + row) * (2 * DM)
                  + (size_t)kv * DM + h * DH + ch * 8;
        cp_async16(SWIZ(sb + (kv ? ASM_V : ASM_K), row, ch), g_kv + go);
    }
    CP_COMMIT();
    CP_WAIT(0);
    __syncthreads();

    float acc_s[2][8][4];
    #pragma unroll
    for (int i = 0; i < 2; i++)
        #pragma unroll
        for (int j = 0; j < 8; j++)
            #pragma unroll
            for (int q = 0; q < 4; q++) acc_s[i][j][q] = 0.0f;

    const int a_r  = lane & 15;
    const int a_c  = lane >> 4;
    const int b_r  = ((lane >> 4) << 3) + (lane & 7);
    const int b_c  = (lane >> 3) & 1;

    #pragma unroll
    for (int t = 0; t < 4; t++) {
        uint32_t qq[2][4], kk[8][2];
        #pragma unroll
        for (int i = 0; i < 2; i++) {
            int row = warp_m + i * 16 + a_r;
            int ch = 2 * t + a_c;
            ldsm_x4(qq[i][0], qq[i][1], qq[i][2], qq[i][3],
                    SWIZ(sb + ASM_Q, row, ch));
        }
        #pragma unroll
        for (int jj = 0; jj < 4; jj++) {
            int row = jj * 16 + b_r;
            int ch = 2 * t + b_c;
            ldsm_x4(kk[2*jj][0], kk[2*jj][1], kk[2*jj+1][0], kk[2*jj+1][1],
                    SWIZ(sb + ASM_K, row, ch));
        }
        #pragma unroll
        for (int i = 0; i < 2; i++)
            #pragma unroll
            for (int j = 0; j < 8; j++)
                mma16816(acc_s[i][j], qq[i][0], qq[i][1], qq[i][2], qq[i][3],
                         kk[j][0], kk[j][1]);
    }

    #pragma unroll
    for (int i = 0; i < 2; i++) {
        #pragma unroll
        for (int half = 0; half < 2; half++) {
            float mx = -1e30f;
            #pragma unroll
            for (int j = 0; j < 8; j++) {
                mx = fmaxf(mx, acc_s[i][j][half*2]);
                mx = fmaxf(mx, acc_s[i][j][half*2+1]);
            }
            mx = fmaxf(mx, __shfl_xor_sync(0xffffffffu, mx, 1));
            mx = fmaxf(mx, __shfl_xor_sync(0xffffffffu, mx, 2));
            float sum = 0.0f;
            #pragma unroll
            for (int j = 0; j < 8; j++) {
                float p0 = expf((acc_s[i][j][half*2]   - mx) * 0.125f);
                float p1 = expf((acc_s[i][j][half*2+1] - mx) * 0.125f);
                acc_s[i][j][half*2]   = p0;
                acc_s[i][j][half*2+1] = p1;
                sum += p0 + p1;
            }
            sum += __shfl_xor_sync(0xffffffffu, sum, 1);
            sum += __shfl_xor_sync(0xffffffffu, sum, 2);
            float inv = 1.0f / sum;
            #pragma unroll
            for (int j = 0; j < 8; j++) {
                acc_s[i][j][half*2]   *= inv;
                acc_s[i][j][half*2+1] *= inv;
            }
        }
    }

    float acc_o[2][8][4];
    #pragma unroll
    for (int i = 0; i < 2; i++)
        #pragma unroll
        for (int j = 0; j < 8; j++)
            #pragma unroll
            for (int q = 0; q < 4; q++) acc_o[i][j][q] = 0.0f;

    #pragma unroll
    for (int t = 0; t < 4; t++) {
        uint32_t pp[2][4];
        #pragma unroll
        for (int i = 0; i < 2; i++) {
            pp[i][0] = pack_h2(acc_s[i][2*t][0],   acc_s[i][2*t][1]);
            pp[i][1] = pack_h2(acc_s[i][2*t][2],   acc_s[i][2*t][3]);
            pp[i][2] = pack_h2(acc_s[i][2*t+1][0], acc_s[i][2*t+1][1]);
            pp[i][3] = pack_h2(acc_s[i][2*t+1][2], acc_s[i][2*t+1][3]);
        }
        uint32_t vv[8][2];
        #pragma unroll
        for (int jj = 0; jj < 4; jj++) {
            int row = t * 16 + (lane & 15);
            int ch = jj * 2 + (lane >> 4);
            ldsm_x4_t(vv[2*jj][0], vv[2*jj][1], vv[2*jj+1][0], vv[2*jj+1][1],
                      SWIZ(sb + ASM_V, row, ch));
        }
        #pragma unroll
        for (int i = 0; i < 2; i++)
            #pragma unroll
            for (int nd = 0; nd < 8; nd++)
                mma16816(acc_o[i][nd], pp[i][0], pp[i][1], pp[i][2], pp[i][3],
                         vv[nd][0], vv[nd][1]);
    }

    const int er = lane >> 2;
    const int ec = (lane & 3) * 2;
    #pragma unroll
    for (int i = 0; i < 2; i++) {
        #pragma unroll
        for (int half = 0; half < 2; half++) {
            int rowl = warp_m + i * 16 + er + half * 8;
            int sq = hmap(n * SEG + rowl);
            size_t gr = ((size_t)(b * S_LEN + sq)) * DM + h * DH;
            #pragma unroll
            for (int nd = 0; nd < 8; nd++) {
                *(uint32_t*)(g_a + gr + nd * 8 + ec) =
                    pack_h2(acc_o[i][nd][half*2], acc_o[i][nd][half*2+1]);
            }
        }
    }
}

// ---------------------------------------------------------------------------
// Launch
// ---------------------------------------------------------------------------
extern "C" void kernel_launch(void* const* d_in, const int* in_sizes, int n_in,
                              void* d_out, int out_size)
{
    const float* x    = (const float*)d_in[0];   // [2,8192,1024]
    const float* wqkv = (const float*)d_in[1];   // [1024,3072]
    const float* wout = (const float*)d_in[2];   // [1024,1024]
    float*       out  = (float*)d_out;           // [2,8192,1024]

    static bool attr_set = false;
    if (!attr_set) {
        cudaFuncSetAttribute(gemm_qkv,
            cudaFuncAttributeMaxDynamicSharedMemorySize, GEMM_SMEM);
        cudaFuncSetAttribute(gemm_out,
            cudaFuncAttributeMaxDynamicSharedMemorySize, GEMM_SMEM);
        cudaFuncSetAttribute(attn_kernel,
            cudaFuncAttributeMaxDynamicSharedMemorySize, ATTN_SMEM);
        attr_set = true;
    }

    // 1. merged prep (one launch)
    prep_kernel<<<PREP_BLKS, 256>>>(x, wqkv, wout);

    // 2. merged Q + K/V projections (2048 CTAs, BN=128, 2 CTAs/SM)
    gemm_qkv<<<2048, 256, GEMM_SMEM>>>();

    // 3. tensor-core segment attention -> fp16 single
    attn_kernel<<<B_SZ * NH * NSEG, 128, ATTN_SMEM>>>();

    // 4. output projection -> fp32 final (1024 CTAs, 2 CTAs/SM)
    gemm_out<<<1024, 256, GEMM_SMEM>>>(out);
}

// round 12
// speedup vs baseline: 1.3539x; 1.0671x over previous
#include <cuda_runtime.h>
#include <cuda_fp16.h>
#include <cstdint>
#include <math.h>

// Problem constants (fixed by the dataset)
#define S_LEN  8192
#define B_SZ   2
#define DM     1024
#define NH     16
#define DH     64
#define SEG    128
#define NSEG   (S_LEN / SEG)     // 64
#define GRID_G 91                // ceil(sqrt(8192))

#define MROWS  (B_SZ * S_LEN)      // 16384
#define KVROWS (B_SZ * S_LEN / 2)  // 8192 compacted K/V rows

// ---------------------------------------------------------------------------
// Scratch (allocation-free rule: __device__ globals)
// ---------------------------------------------------------------------------
__device__ __half  g_x   [MROWS * DM];          // x fp16
__device__ __half  g_q   [MROWS * DM];          // Q fp16 single
__device__ __half  g_kv  [KVROWS * 2 * DM];     // compact [K|V] fp16
__device__ __half  g_a   [MROWS * DM];          // attn-out fp16
__device__ __half  g_wq  [3 * DM * DM];         // W_qkv^T fp16 [3072,1024]
__device__ __half  g_wo  [DM * DM];             // W_out^T fp16 [1024,1024]
__device__ int     g_rowkv[KVROWS];             // gathered A rows for K/V GEMM

// ---------------------------------------------------------------------------
// PTX helpers (compute_103-safe subset: ldmatrix / mma.sync / cp.async)
// ---------------------------------------------------------------------------
__device__ __forceinline__ uint32_t smem_to_u32(const void* p) {
    uint32_t a;
    asm("{ .reg .u64 t; cvta.to.shared.u64 t, %1; cvt.u32.u64 %0, t; }"
        : "=r"(a) : "l"(p));
    return a;
}
__device__ __forceinline__ void cp_async16(uint32_t saddr, const void* gptr) {
    asm volatile("cp.async.cg.shared.global [%0], [%1], 16;"
                 :: "r"(saddr), "l"(gptr));
}
#define CP_COMMIT() asm volatile("cp.async.commit_group;")
#define CP_WAIT(n)  asm volatile("cp.async.wait_group %0;" :: "n"(n))

__device__ __forceinline__ void ldsm_x4(uint32_t& r0, uint32_t& r1,
                                        uint32_t& r2, uint32_t& r3,
                                        uint32_t addr) {
    asm volatile("ldmatrix.sync.aligned.m8n8.x4.shared.b16 {%0,%1,%2,%3}, [%4];"
                 : "=r"(r0), "=r"(r1), "=r"(r2), "=r"(r3) : "r"(addr));
}
__device__ __forceinline__ void ldsm_x4_t(uint32_t& r0, uint32_t& r1,
                                          uint32_t& r2, uint32_t& r3,
                                          uint32_t addr) {
    asm volatile("ldmatrix.sync.aligned.m8n8.x4.trans.shared.b16 {%0,%1,%2,%3}, [%4];"
                 : "=r"(r0), "=r"(r1), "=r"(r2), "=r"(r3) : "r"(addr));
}
__device__ __forceinline__ void mma16816(float* c,
                                         uint32_t a0, uint32_t a1,
                                         uint32_t a2, uint32_t a3,
                                         uint32_t b0, uint32_t b1) {
    asm volatile(
        "mma.sync.aligned.m16n8k16.row.col.f32.f16.f16.f32 "
        "{%0,%1,%2,%3}, {%4,%5,%6,%7}, {%8,%9}, {%0,%1,%2,%3};"
        : "+f"(c[0]), "+f"(c[1]), "+f"(c[2]), "+f"(c[3])
        : "r"(a0), "r"(a1), "r"(a2), "r"(a3), "r"(b0), "r"(b1));
}

__device__ __forceinline__ uint32_t pack_h2(float a, float b) {
    __half2 t = __halves2half2(__float2half_rn(a), __float2half_rn(b));
    return *(uint32_t*)&t;
}

// ---------------------------------------------------------------------------
// Closed-form boustrophedon map
// ---------------------------------------------------------------------------
__device__ __forceinline__ int hmap(int lp) {
    int r = lp / GRID_G;
    int c = lp % GRID_G;
    int vr = min(GRID_G, S_LEN - r * GRID_G);
    return ((r & 1) == 0) ? (r * GRID_G + c) : (r * GRID_G + vr - 1 - c);
}

// ---------------------------------------------------------------------------
// Merged prep: cvt (16384 blocks) | W_qkv^T (3072) | W_out^T (1024) | rowkv (32)
// ---------------------------------------------------------------------------
#define PREP_CVT_BLKS   16384
#define PREP_TQ_BLKS    3072
#define PREP_TO_BLKS    1024
#define PREP_RK_BLKS    32
#define PREP_BLKS (PREP_CVT_BLKS + PREP_TQ_BLKS + PREP_TO_BLKS + PREP_RK_BLKS)

__global__ __launch_bounds__(256) void prep_kernel(
    const float* __restrict__ x,
    const float* __restrict__ wqkv,
    const float* __restrict__ wout)
{
    __shared__ float t[32][33];
    const int bx = blockIdx.x;
    const int tid = threadIdx.x;

    if (bx < PREP_CVT_BLKS) {
        int i = bx * 256 + tid;
        float4 v = ((const float4*)x)[i];
        ((uint32_t*)g_x)[2 * i]     = pack_h2(v.x, v.y);
        ((uint32_t*)g_x)[2 * i + 1] = pack_h2(v.z, v.w);
        return;
    }
    if (bx < PREP_CVT_BLKS + PREP_TQ_BLKS + PREP_TO_BLKS) {
        const float* W; __half* T; int N, tb;
        if (bx < PREP_CVT_BLKS + PREP_TQ_BLKS) {
            W = wqkv; T = g_wq; N = 3 * DM; tb = bx - PREP_CVT_BLKS;
        } else {
            W = wout; T = g_wo; N = DM; tb = bx - PREP_CVT_BLKS - PREP_TQ_BLKS;
        }
        int nblk = N / 32;
        int n0 = (tb % nblk) * 32, k0 = (tb / nblk) * 32;
        int tx = tid & 31, ty = tid >> 5;
        #pragma unroll
        for (int i = 0; i < 4; i++)
            t[ty + 8 * i][tx] = W[(size_t)(k0 + ty + 8 * i) * N + n0 + tx];
        __syncthreads();
        #pragma unroll
        for (int i = 0; i < 4; i++) {
            size_t o = (size_t)(n0 + ty + 8 * i) * DM + k0 + tx;
            T[o] = __float2half_rn(t[tx][ty + 8 * i]);
        }
        return;
    }
    int i = (bx - (PREP_BLKS - PREP_RK_BLKS)) * 256 + tid;
    int b = i >> 12;
    int r = i & 4095;
    int n = r >> 6, j = r & 63;
    g_rowkv[i] = b * S_LEN + hmap(n * SEG + 2 * j);
}

// ---------------------------------------------------------------------------
// Unified GEMM core: BM=128, BN=128, BK=64, 256 threads, 3-stage cp.async,
// 2 CTAs/SM. Warp tile 64x32. Per barrier window: 4 k-slabs (24 ldsm, 64 MMA)
// so ldsm of slab k+1 overlaps MMAs of slab k.
// ---------------------------------------------------------------------------
#define GBM 128
#define GBN 128
#define GBK 64
#define KD  1024
#define ITERS (KD / GBK)               // 16
#define RSB 144                        // 64 fp16 (128B) + 16B pad
#define OFF_B   (GBM * RSB)            // 18432
#define STAGE_BYTES ((GBM + GBN) * RSB)  // 36864
#define NSTAGE  3
#define GEMM_SMEM (NSTAGE * STAGE_BYTES) // 110592

template<bool FP16OUT>
__device__ __forceinline__ void gemm_core128(
    int m0, int n0, int N,
    const __half* __restrict__ A, const __half* __restrict__ B,
    const int* __restrict__ rowlist,
    float* __restrict__ C, __half* __restrict__ Ch,
    char* smem, int* srl)
{
    const uint32_t sb = smem_to_u32(smem);
    const int tid  = threadIdx.x;
    const int wid  = tid >> 5;
    const int lane = tid & 31;

    if (tid < GBM) srl[tid] = rowlist ? rowlist[m0 + tid] : (m0 + tid);
    __syncthreads();

    const int warp_m = (wid & 1) * 64;
    const int warp_n = (wid >> 1) * 32;

    float acc[4][4][4];
    #pragma unroll
    for (int i = 0; i < 4; i++)
        #pragma unroll
        for (int j = 0; j < 4; j++)
            #pragma unroll
            for (int q = 0; q < 4; q++) acc[i][j][q] = 0.0f;

    // 2048 16B chunks per stage, 8 per thread
    auto load_stage = [&](int it, int stage) {
        const uint32_t stg = sb + stage * STAGE_BYTES;
        const int k0 = it * GBK;
        #pragma unroll
        for (int i = 0; i < 8; i++) {
            int c = i * 256 + tid;
            const __half* g;
            uint32_t soff;
            if (c < 1024) {            // A: 128 rows x 8 chunks
                int row = c >> 3, kc = c & 7;
                g = A + (size_t)srl[row] * KD + k0 + kc * 8;
                soff = row * RSB + kc * 16;
            } else {                   // B: 128 rows x 8 chunks
                int c2 = c - 1024;
                int row = c2 >> 3, kc = c2 & 7;
                g = B + (size_t)(n0 + row) * KD + k0 + kc * 8;
                soff = OFF_B + row * RSB + kc * 16;
            }
            cp_async16(stg + soff, g);
        }
    };

    load_stage(0, 0); CP_COMMIT();
    load_stage(1, 1); CP_COMMIT();

    const int a_row  = lane & 15;
    const int a_byte = (lane >> 4) << 4;
    const int b_row  = ((lane >> 4) << 3) + (lane & 7);
    const int b_byte = ((lane >> 3) & 1) << 4;

    #pragma unroll 1
    for (int it = 0; it < ITERS; ++it) {
        if (it + 1 < ITERS) { CP_WAIT(1); } else { CP_WAIT(0); }
        __syncthreads();

        if (it + 2 < ITERS) {
            load_stage(it + 2, (it + 2) % NSTAGE);
            CP_COMMIT();
        }

        const uint32_t stg = sb + (it % NSTAGE) * STAGE_BYTES;
        const uint32_t aARow = stg + (warp_m + a_row) * RSB + a_byte;
        const uint32_t aBRow = stg + OFF_B + (warp_n + b_row) * RSB + b_byte;

        #pragma unroll
        for (int kc = 0; kc < 4; kc++) {     // 4 k-slabs of 16 elems
            const uint32_t kb = kc * 32;
            uint32_t aa[4][4], bb[4][2];
            #pragma unroll
            for (int i = 0; i < 4; i++)
                ldsm_x4(aa[i][0], aa[i][1], aa[i][2], aa[i][3],
                        aARow + i * 16 * RSB + kb);
            #pragma unroll
            for (int jj = 0; jj < 2; jj++)
                ldsm_x4(bb[2*jj][0], bb[2*jj][1], bb[2*jj+1][0], bb[2*jj+1][1],
                        aBRow + jj * 16 * RSB + kb);
            #pragma unroll
            for (int i = 0; i < 4; i++)
                #pragma unroll
                for (int j = 0; j < 4; j++)
                    mma16816(acc[i][j], aa[i][0], aa[i][1], aa[i][2], aa[i][3],
                             bb[j][0], bb[j][1]);
        }
    }

    const int er = lane >> 2;
    const int ec = (lane & 3) * 2;
    if (FP16OUT) {
        #pragma unroll
        for (int i = 0; i < 4; i++)
            #pragma unroll
            for (int j = 0; j < 4; j++) {
                int row = m0 + warp_m + i * 16 + er;
                int col = n0 + warp_n + j * 8 + ec;
                *(uint32_t*)(Ch + (size_t)row * N + col) =
                    pack_h2(acc[i][j][0], acc[i][j][1]);
                *(uint32_t*)(Ch + (size_t)(row + 8) * N + col) =
                    pack_h2(acc[i][j][2], acc[i][j][3]);
            }
    } else {
        #pragma unroll
        for (int i = 0; i < 4; i++)
            #pragma unroll
            for (int j = 0; j < 4; j++) {
                int row = m0 + warp_m + i * 16 + er;
                int col = n0 + warp_n + j * 8 + ec;
                float* p0 = C + (size_t)row * N + col;
                float* p1 = C + (size_t)(row + 8) * N + col;
                p0[0] = acc[i][j][0]; p0[1] = acc[i][j][1];
                p1[0] = acc[i][j][2]; p1[1] = acc[i][j][3];
            }
    }
}

// Merged Q + K/V projection: 2048 CTAs (1024 Q tiles + 1024 KV tiles).
__global__ __launch_bounds__(256, 2) void gemm_qkv() {
    extern __shared__ char smem[];
    __shared__ int srl[GBM];
    int bx = blockIdx.x;
    if (bx < 1024) {
        gemm_core128<true>((bx >> 3) * GBM, (bx & 7) * GBN, DM,
                           g_x, g_wq, nullptr, nullptr, g_q, smem, srl);
    } else {
        int t = bx - 1024;
        gemm_core128<true>((t >> 4) * GBM, (t & 15) * GBN, 2 * DM,
                           g_x, g_wq + (size_t)DM * DM, g_rowkv,
                           nullptr, g_kv, smem, srl);
    }
}

// Output projection: 1024 CTAs, fp32 out.
__global__ __launch_bounds__(256, 2) void gemm_out(float* __restrict__ C) {
    extern __shared__ char smem[];
    __shared__ int srl[GBM];
    int bx = blockIdx.x;
    gemm_core128<false>((bx >> 3) * GBM, (bx & 7) * GBN, DM,
                        g_a, g_wo, nullptr, C, nullptr, smem, srl);
}

// ---------------------------------------------------------------------------
// Tensor-core segment attention (fp16 HMMA, softmax in fragments).
// Q, K, V, P all single fp16.  One block per (b, h, seg): 128 threads.
// smem: swizzled fp16 tiles Q[128x64], K[64x64], V[64x64] = 32KB.
// ---------------------------------------------------------------------------
#define ASM_Q  0
#define ASM_K  16384
#define ASM_V  24576
#define ATTN_SMEM 32768
#define SWIZ(base, row, ch) ((base) + (row) * 128 + ((((ch) ^ ((row) & 7))) << 4))

__global__ __launch_bounds__(128) void attn_kernel() {
    extern __shared__ char asmem[];
    const uint32_t sb = smem_to_u32(asmem);

    const int bid = blockIdx.x;
    const int n = bid % NSEG;
    const int h = (bid / NSEG) % NH;
    const int b = bid / (NSEG * NH);
    const int tid = threadIdx.x;
    const int lane = tid & 31;
    const int wid = tid >> 5;
    const int warp_m = wid * 32;

    #pragma unroll
    for (int i = 0; i < 8; i++) {
        int c = i * 128 + tid;
        int row = c >> 3, ch = c & 7;
        int sq = hmap(n * SEG + row);
        const __half* g = g_q + ((size_t)(b * S_LEN + sq)) * DM + h * DH + ch * 8;
        cp_async16(SWIZ(sb + ASM_Q, row, ch), g);
    }
    #pragma unroll
    for (int i = 0; i < 8; i++) {
        int c = i * 128 + tid;
        int kv  = c >> 9;
        int rc  = c & 511;
        int row = rc >> 3, ch = rc & 7;
        size_t go = ((size_t)b * 4096 + n * 64 + row) * (2 * DM)
                  + (size_t)kv * DM + h * DH + ch * 8;
        cp_async16(SWIZ(sb + (kv ? ASM_V : ASM_K), row, ch), g_kv + go);
    }
    CP_COMMIT();
    CP_WAIT(0);
    __syncthreads();

    float acc_s[2][8][4];
    #pragma unroll
    for (int i = 0; i < 2; i++)
        #pragma unroll
        for (int j = 0; j < 8; j++)
            #pragma unroll
            for (int q = 0; q < 4; q++) acc_s[i][j][q] = 0.0f;

    const int a_r  = lane & 15;
    const int a_c  = lane >> 4;
    const int b_r  = ((lane >> 4) << 3) + (lane & 7);
    const int b_c  = (lane >> 3) & 1;

    #pragma unroll
    for (int t = 0; t < 4; t++) {
        uint32_t qq[2][4], kk[8][2];
        #pragma unroll
        for (int i = 0; i < 2; i++) {
            int row = warp_m + i * 16 + a_r;
            int ch = 2 * t + a_c;
            ldsm_x4(qq[i][0], qq[i][1], qq[i][2], qq[i][3],
                    SWIZ(sb + ASM_Q, row, ch));
        }
        #pragma unroll
        for (int jj = 0; jj < 4; jj++) {
            int row = jj * 16 + b_r;
            int ch = 2 * t + b_c;
            ldsm_x4(kk[2*jj][0], kk[2*jj][1], kk[2*jj+1][0], kk[2*jj+1][1],
                    SWIZ(sb + ASM_K, row, ch));
        }
        #pragma unroll
        for (int i = 0; i < 2; i++)
            #pragma unroll
            for (int j = 0; j < 8; j++)
                mma16816(acc_s[i][j], qq[i][0], qq[i][1], qq[i][2], qq[i][3],
                         kk[j][0], kk[j][1]);
    }

    #pragma unroll
    for (int i = 0; i < 2; i++) {
        #pragma unroll
        for (int half = 0; half < 2; half++) {
            float mx = -1e30f;
            #pragma unroll
            for (int j = 0; j < 8; j++) {
                mx = fmaxf(mx, acc_s[i][j][half*2]);
                mx = fmaxf(mx, acc_s[i][j][half*2+1]);
            }
            mx = fmaxf(mx, __shfl_xor_sync(0xffffffffu, mx, 1));
            mx = fmaxf(mx, __shfl_xor_sync(0xffffffffu, mx, 2));
            float sum = 0.0f;
            #pragma unroll
            for (int j = 0; j < 8; j++) {
                float p0 = expf((acc_s[i][j][half*2]   - mx) * 0.125f);
                float p1 = expf((acc_s[i][j][half*2+1] - mx) * 0.125f);
                acc_s[i][j][half*2]   = p0;
                acc_s[i][j][half*2+1] = p1;
                sum += p0 + p1;
            }
            sum += __shfl_xor_sync(0xffffffffu, sum, 1);
            sum += __shfl_xor_sync(0xffffffffu, sum, 2);
            float inv = 1.0f / sum;
            #pragma unroll
            for (int j = 0; j < 8; j++) {
                acc_s[i][j][half*2]   *= inv;
                acc_s[i][j][half*2+1] *= inv;
            }
        }
    }

    float acc_o[2][8][4];
    #pragma unroll
    for (int i = 0; i < 2; i++)
        #pragma unroll
        for (int j = 0; j < 8; j++)
            #pragma unroll
            for (int q = 0; q < 4; q++) acc_o[i][j][q] = 0.0f;

    #pragma unroll
    for (int t = 0; t < 4; t++) {
        uint32_t pp[2][4];
        #pragma unroll
        for (int i = 0; i < 2; i++) {
            pp[i][0] = pack_h2(acc_s[i][2*t][0],   acc_s[i][2*t][1]);
            pp[i][1] = pack_h2(acc_s[i][2*t][2],   acc_s[i][2*t][3]);
            pp[i][2] = pack_h2(acc_s[i][2*t+1][0], acc_s[i][2*t+1][1]);
            pp[i][3] = pack_h2(acc_s[i][2*t+1][2], acc_s[i][2*t+1][3]);
        }
        uint32_t vv[8][2];
        #pragma unroll
        for (int jj = 0; jj < 4; jj++) {
            int row = t * 16 + (lane & 15);
            int ch = jj * 2 + (lane >> 4);
            ldsm_x4_t(vv[2*jj][0], vv[2*jj][1], vv[2*jj+1][0], vv[2*jj+1][1],
                      SWIZ(sb + ASM_V, row, ch));
        }
        #pragma unroll
        for (int i = 0; i < 2; i++)
            #pragma unroll
            for (int nd = 0; nd < 8; nd++)
                mma16816(acc_o[i][nd], pp[i][0], pp[i][1], pp[i][2], pp[i][3],
                         vv[nd][0], vv[nd][1]);
    }

    const int er = lane >> 2;
    const int ec = (lane & 3) * 2;
    #pragma unroll
    for (int i = 0; i < 2; i++) {
        #pragma unroll
        for (int half = 0; half < 2; half++) {
            int rowl = warp_m + i * 16 + er + half * 8;
            int sq = hmap(n * SEG + rowl);
            size_t gr = ((size_t)(b * S_LEN + sq)) * DM + h * DH;
            #pragma unroll
            for (int nd = 0; nd < 8; nd++) {
                *(uint32_t*)(g_a + gr + nd * 8 + ec) =
                    pack_h2(acc_o[i][nd][half*2], acc_o[i][nd][half*2+1]);
            }
        }
    }
}

// ---------------------------------------------------------------------------
// Launch
// ---------------------------------------------------------------------------
extern "C" void kernel_launch(void* const* d_in, const int* in_sizes, int n_in,
                              void* d_out, int out_size)
{
    const float* x    = (const float*)d_in[0];   // [2,8192,1024]
    const float* wqkv = (const float*)d_in[1];   // [1024,3072]
    const float* wout = (const float*)d_in[2];   // [1024,1024]
    float*       out  = (float*)d_out;           // [2,8192,1024]

    static bool attr_set = false;
    if (!attr_set) {
        cudaFuncSetAttribute(gemm_qkv,
            cudaFuncAttributeMaxDynamicSharedMemorySize, GEMM_SMEM);
        cudaFuncSetAttribute(gemm_out,
            cudaFuncAttributeMaxDynamicSharedMemorySize, GEMM_SMEM);
        cudaFuncSetAttribute(attn_kernel,
            cudaFuncAttributeMaxDynamicSharedMemorySize, ATTN_SMEM);
        attr_set = true;
    }

    // 1. merged prep (one launch)
    prep_kernel<<<PREP_BLKS, 256>>>(x, wqkv, wout);

    // 2. merged Q + K/V projections (2048 CTAs, BK=64, 2 CTAs/SM)
    gemm_qkv<<<2048, 256, GEMM_SMEM>>>();

    // 3. tensor-core segment attention -> fp16 single
    attn_kernel<<<B_SZ * NH * NSEG, 128, ATTN_SMEM>>>();

    // 4. output projection -> fp32 final (1024 CTAs, 2 CTAs/SM)
    gemm_out<<<1024, 256, GEMM_SMEM>>>(out);
}